// round 2
// baseline (speedup 1.0000x reference)
#include <cuda_runtime.h>

#define NL 4
#define H 32
#define TT 64
#define NB 8                 // batches per warp (lane = hidden index j)
#define WARPS_CTA 4
#define THREADS (WARPS_CTA * 32)

typedef unsigned long long u64;

// k-packed weights: for kpair m (k=2m,2m+1), gatepair gp, output j:
// ulonglong2 = ( pack(W[g][2m],W[g][2m+1]) for g=2gp, same for g=2gp+1 )
__device__ ulonglong2 g_Whh2[NL][16][2][32];
__device__ ulonglong2 g_Wih2[NL - 1][16][2][32];
__device__ ulonglong2 g_Wih0_2[2][32];   // single kpair (k=0,1), [gp][j]
__device__ float4 g_bias[NL][32];        // (i,f,g,o) per j
__device__ float  g_Wlin[H];
__device__ float  g_blin;

__device__ __forceinline__ u64 pk2(float a, float b) {
    u64 r; asm("mov.b64 %0, {%1, %2};" : "=l"(r) : "f"(a), "f"(b)); return r;
}
__device__ __forceinline__ float2 upk(u64 v) {
    float2 r; asm("mov.b64 {%0, %1}, %2;" : "=f"(r.x), "=f"(r.y) : "l"(v)); return r;
}
// Packed fp32x2 FMA (Blackwell): d = a*b + c elementwise on both 32-bit halves.
__device__ __forceinline__ u64 ffma2(u64 a, u64 b, u64 c) {
    u64 d; asm("fma.rn.f32x2 %0, %1, %2, %3;" : "=l"(d) : "l"(a), "l"(b), "l"(c)); return d;
}

__device__ __forceinline__ float sigm(float v) {
    return __fdividef(1.0f, 1.0f + __expf(-v));
}
__device__ __forceinline__ float tanh_(float v) {
    return __fdividef(2.0f, 1.0f + __expf(-2.0f * v)) - 1.0f;
}

// acc[g][b] += sum over k of W[g][j][k] * h[b][k], k packed in f32x2 pairs.
// wp = &W[l][0][0][0] + j ; hrow = &h_stage[wid][l][0][0]
__device__ __forceinline__ void mat_acc(const ulonglong2* __restrict__ wp,
                                        const float* __restrict__ hrow,
                                        u64 acc[4][NB]) {
#pragma unroll 2
    for (int m2 = 0; m2 < 8; ++m2) {
        // kpair 2*m2   : gates (i,f) and (g,o)
        ulonglong2 wa0 = wp[(4 * m2 + 0) * 32];
        ulonglong2 wb0 = wp[(4 * m2 + 1) * 32];
        // kpair 2*m2+1
        ulonglong2 wa1 = wp[(4 * m2 + 2) * 32];
        ulonglong2 wb1 = wp[(4 * m2 + 3) * 32];
#pragma unroll
        for (int b = 0; b < NB; ++b) {
            ulonglong2 v = *(const ulonglong2*)(hrow + b * H + 4 * m2); // LDS.128 broadcast
            acc[0][b] = ffma2(v.x, wa0.x, acc[0][b]);
            acc[1][b] = ffma2(v.x, wa0.y, acc[1][b]);
            acc[2][b] = ffma2(v.x, wb0.x, acc[2][b]);
            acc[3][b] = ffma2(v.x, wb0.y, acc[3][b]);
            acc[0][b] = ffma2(v.y, wa1.x, acc[0][b]);
            acc[1][b] = ffma2(v.y, wa1.y, acc[1][b]);
            acc[2][b] = ffma2(v.y, wb1.x, acc[2][b]);
            acc[3][b] = ffma2(v.y, wb1.y, acc[3][b]);
        }
    }
}

__global__ void prep_kernel(const float* __restrict__ W_ih0, const float* __restrict__ W_ih,
                            const float* __restrict__ W_hh, const float* __restrict__ b_ih,
                            const float* __restrict__ b_hh, const float* __restrict__ W_lin,
                            const float* __restrict__ b_lin) {
    int i = blockIdx.x * blockDim.x + threadIdx.x;
    // Whh2: 16384 floats: [l][m][gp][j][c], c: {g=2gp+(c>>1), k=2m+(c&1)}
    if (i < NL * 16 * 2 * 32 * 4) {
        int c = i & 3, j = (i >> 2) & 31, gp = (i >> 7) & 1, m = (i >> 8) & 15, l = i >> 12;
        int g = gp * 2 + (c >> 1), k = 2 * m + (c & 1);
        ((float*)g_Whh2)[i] = W_hh[l * 4096 + (g * 32 + j) * 32 + k];
    }
    if (i < (NL - 1) * 16 * 2 * 32 * 4) {
        int c = i & 3, j = (i >> 2) & 31, gp = (i >> 7) & 1, m = (i >> 8) & 15, l = i >> 12;
        int g = gp * 2 + (c >> 1), k = 2 * m + (c & 1);
        ((float*)g_Wih2)[i] = W_ih[l * 4096 + (g * 32 + j) * 32 + k];
    }
    if (i < 2 * 32 * 4) {
        int c = i & 3, j = (i >> 2) & 31, gp = i >> 7;
        int g = gp * 2 + (c >> 1), k = c & 1;
        ((float*)g_Wih0_2)[i] = W_ih0[(g * 32 + j) * 2 + k];
    }
    if (i < NL * 32 * 4) {
        int g = i & 3, j = (i >> 2) & 31, l = i >> 7;
        ((float*)g_bias)[i] = b_ih[l * 128 + g * 32 + j] + b_hh[l * 128 + g * 32 + j];
    }
    if (i < H) g_Wlin[i] = W_lin[i];
    if (i == 0) g_blin = b_lin[0];
}

__global__ void __launch_bounds__(THREADS, 4)
lstm_kernel(const float* __restrict__ x, float* __restrict__ out) {
    __shared__ __align__(16) float h_stage[WARPS_CTA][NL][NB][H];
    const int wid = threadIdx.x >> 5;
    const int j = threadIdx.x & 31;
    const int base = (blockIdx.x * WARPS_CTA + wid) * NB;

    float c[NL][NB];
#pragma unroll
    for (int l = 0; l < NL; ++l)
#pragma unroll
        for (int b = 0; b < NB; ++b) {
            c[l][b] = 0.f;
            h_stage[wid][l][b][j] = 0.f;
        }
    __syncwarp();

    const float* xb = x + (size_t)base * 192;

#pragma unroll 1
    for (int t = 0; t < TT; ++t) {
        u64 acc[4][NB];

        // ---------------- layer 0: ih (K=2, from x) + hh ----------------
        {
            ulonglong2 w0 = g_Wih0_2[0][j];   // (wi, wf) packed over k=0,1
            ulonglong2 w1 = g_Wih0_2[1][j];   // (wg, wo)
#pragma unroll
            for (int b = 0; b < NB; ++b) {
                float x0 = __ldg(xb + (size_t)b * 192 + t);
                float x1 = __ldg(xb + (size_t)b * 192 + 64 + t);
                u64 xv = pk2(x0, x1);
                acc[0][b] = ffma2(xv, w0.x, 0ull);
                acc[1][b] = ffma2(xv, w0.y, 0ull);
                acc[2][b] = ffma2(xv, w1.x, 0ull);
                acc[3][b] = ffma2(xv, w1.y, 0ull);
            }
        }
        mat_acc(&g_Whh2[0][0][0][0] + j, &h_stage[wid][0][0][0], acc);
        __syncwarp();
        {
            float4 bb = g_bias[0][j];
#pragma unroll
            for (int b = 0; b < NB; ++b) {
                float2 a0 = upk(acc[0][b]), a1 = upk(acc[1][b]);
                float2 a2 = upk(acc[2][b]), a3 = upk(acc[3][b]);
                float ii = sigm(a0.x + a0.y + bb.x);
                float ff = sigm(a1.x + a1.y + bb.y);
                float gg = tanh_(a2.x + a2.y + bb.z);
                float oo = sigm(a3.x + a3.y + bb.w);
                float cn = ff * c[0][b] + ii * gg;
                c[0][b] = cn;
                h_stage[wid][0][b][j] = oo * tanh_(cn);
            }
        }
        __syncwarp();

        // ---------------- layers 1..3 (fully unrolled; c stays in regs) ----
#pragma unroll
        for (int l = 1; l < NL; ++l) {
#pragma unroll
            for (int b = 0; b < NB; ++b) {
                acc[0][b] = 0ull; acc[1][b] = 0ull; acc[2][b] = 0ull; acc[3][b] = 0ull;
            }
            mat_acc(&g_Wih2[l - 1][0][0][0] + j, &h_stage[wid][l - 1][0][0], acc);
            mat_acc(&g_Whh2[l][0][0][0] + j,     &h_stage[wid][l][0][0],     acc);
            __syncwarp();
            {
                float4 bb = g_bias[l][j];
#pragma unroll
                for (int b = 0; b < NB; ++b) {
                    float2 a0 = upk(acc[0][b]), a1 = upk(acc[1][b]);
                    float2 a2 = upk(acc[2][b]), a3 = upk(acc[3][b]);
                    float ii = sigm(a0.x + a0.y + bb.x);
                    float ff = sigm(a1.x + a1.y + bb.y);
                    float gg = tanh_(a2.x + a2.y + bb.z);
                    float oo = sigm(a3.x + a3.y + bb.w);
                    float cn = ff * c[l][b] + ii * gg;
                    c[l][b] = cn;
                    h_stage[wid][l][b][j] = oo * tanh_(cn);
                }
            }
            __syncwarp();
        }
    }

    // ---------------- head: out[b] = sigmoid(h3[b] . Wlin + blin) ----------
    float wl = g_Wlin[j];
    float bl = g_blin;
#pragma unroll
    for (int b = 0; b < NB; ++b) {
        float s = h_stage[wid][NL - 1][b][j] * wl;
#pragma unroll
        for (int off = 16; off > 0; off >>= 1)
            s += __shfl_xor_sync(0xffffffffu, s, off);
        if (j == 0) out[base + b] = sigm(s + bl);
    }
}

extern "C" void kernel_launch(void* const* d_in, const int* in_sizes, int n_in,
                              void* d_out, int out_size) {
    const float* x     = (const float*)d_in[0];
    const float* W_ih0 = (const float*)d_in[1];
    const float* W_ih  = (const float*)d_in[2];
    const float* W_hh  = (const float*)d_in[3];
    const float* b_ih  = (const float*)d_in[4];
    const float* b_hh  = (const float*)d_in[5];
    const float* W_lin = (const float*)d_in[6];
    const float* b_lin = (const float*)d_in[7];

    prep_kernel<<<64, 256>>>(W_ih0, W_ih, W_hh, b_ih, b_hh, W_lin, b_lin);

    int B = in_sizes[0] / (3 * TT);                 // 16384
    int blocks = B / (WARPS_CTA * NB);              // 512
    lstm_kernel<<<blocks, THREADS>>>(x, (float*)d_out);
}